// round 15
// baseline (speedup 1.0000x reference)
#include <cuda_runtime.h>
#include <cuda_bf16.h>

// BundleAdjustment, round 14: R12 revert + live-range shrink (no forced reg caps).
//  - paired pose gathers (optimal line-touches), 2 edges/thread, streaming ld/st
//  - target loaded per-edge as float2 at point of use (shorter live ranges,
//    aiming for natural 32 regs WITHOUT spills; R13 proved forced caps spill)

#define R_MIN   0.5f
#define R_MAX   30.0f
#define BINS    512.0f
#define BEAMS   512.0f
#define FOV_H   2.0943951f

#define P_NUM   8192

// Scratch: pose table, 32B per pose: [2i]=(tx,ty,tz,qx)  [2i+1]=(qy,qz,qw,0)
__device__ float4 g_pose[2 * P_NUM];   // 256 KB

// ---------------- Tiny pose prepass ----------------
__global__ __launch_bounds__(256) void pose_prepass(
    const float* __restrict__ poses,
    const float* __restrict__ init_poses,
    float*       __restrict__ out_pose,      // out + 2E
    int P7)
{
    const int tid = blockIdx.x * blockDim.x + threadIdx.x;
    const int nv  = P7 >> 2;                 // 14336 float4 residuals
    if (tid < nv) {
        const float4 a = __ldcg(((const float4*)poses) + tid);
        const float4 b = __ldcg(((const float4*)init_poses) + tid);
        float4 r = make_float4(a.x - b.x, a.y - b.y, a.z - b.z, a.w - b.w);
        __stcg(((float4*)out_pose) + tid, r);
    }
    if (tid < P_NUM) {
        const float* p = poses + 7 * tid;
        g_pose[2 * tid]     = make_float4(p[0], p[1], p[2], p[3]);
        g_pose[2 * tid + 1] = make_float4(p[4], p[5], p[6], 0.0f);
    }
}

// ---------------- Main ----------------
__device__ __forceinline__ float4 shfl_xor_f4(float4 v, int m)
{
    float4 r;
    r.x = __shfl_xor_sync(0xFFFFFFFFu, v.x, m);
    r.y = __shfl_xor_sync(0xFFFFFFFFu, v.y, m);
    r.z = __shfl_xor_sync(0xFFFFFFFFu, v.z, m);
    r.w = __shfl_xor_sync(0xFFFFFFFFu, v.w, m);
    return r;
}

// Cooperatively gather pose[idx] (32B) per lane via lane-pairing. Bit-exact.
__device__ __forceinline__ void gather_pose_paired(int idx, int odd,
                                                   float4& lo, float4& hi)
{
    const int idx_part = __shfl_xor_sync(0xFFFFFFFFu, idx, 1);
    const int s_even = odd ? idx_part : idx;
    const int s_odd  = odd ? idx      : idx_part;

    const float4 fa = __ldg(&g_pose[2 * s_even + odd]);  // pair covers both halves of pose[s_even]
    const float4 fb = __ldg(&g_pose[2 * s_odd + odd]);   // pair covers both halves of pose[s_odd]

    const float4 fa_x = shfl_xor_f4(fa, 1);
    const float4 fb_x = shfl_xor_f4(fb, 1);

    lo = odd ? fb_x : fa;
    hi = odd ? fb   : fa_x;
}

__device__ __forceinline__ float2 finish_edge(float2 pc, float ph,
                                              const float4& sa, const float4& sb,
                                              const float4& ta, const float4& tb,
                                              float2 tg)
{
    float st, ct, sph, cph;
    __sincosf(pc.y, &st, &ct);
    __sincosf(ph,   &sph, &cph);
    const float rcp = pc.x * cph;
    float vx = rcp * ct;
    float vy = rcp * st;
    float vz = pc.x * sph;

    {
        const float qx = sa.w, qy = sb.x, qz = sb.y, qw = sb.z;
        const float tx = 2.0f * (qy * vz - qz * vy);
        const float ty = 2.0f * (qz * vx - qx * vz);
        const float tz = 2.0f * (qx * vy - qy * vx);
        const float rx = vx + qw * tx + (qy * tz - qz * ty);
        const float ry = vy + qw * ty + (qz * tx - qx * tz);
        const float rz = vz + qw * tz + (qx * ty - qy * tx);
        vx = rx + sa.x; vy = ry + sa.y; vz = rz + sa.z;
    }

    vx -= ta.x; vy -= ta.y; vz -= ta.z;
    float lx, ly, lz;
    {
        const float qx = -ta.w, qy = -tb.x, qz = -tb.y, qw = tb.z;
        const float tx = 2.0f * (qy * vz - qz * vy);
        const float ty = 2.0f * (qz * vx - qx * vz);
        const float tz = 2.0f * (qx * vy - qy * vx);
        lx = vx + qw * tx + (qy * tz - qz * ty);
        ly = vy + qw * ty + (qz * tx - qx * tz);
        lz = vz + qw * tz + (qx * ty - qy * tx);
    }

    const float r3 = sqrtf(lx * lx + ly * ly + lz * lz);
    const float th = atan2f(ly, lx);

    float2 res;
    res.x = (r3 - tg.x) * (BINS  / (R_MAX - R_MIN));
    res.y = (th - tg.y) * (BEAMS / FOV_H);
    return res;
}

__global__ __launch_bounds__(256) void ba_main(
    const float* __restrict__ patch_coords,  // float2 per patch
    const float* __restrict__ elev,
    const float* __restrict__ init_elev,
    const float* __restrict__ target,        // float2 per edge
    const int*   __restrict__ src_idx,
    const int*   __restrict__ tgt_idx,
    const int*   __restrict__ patch_idx,
    float*       __restrict__ out,           // residual_proj base
    float*       __restrict__ out_elev,      // out + 2E + P7
    int E)
{
    const int tid   = blockIdx.x * blockDim.x + threadIdx.x;
    const int pairs = E >> 1;                // E % 512 == 0: whole warps only
    if (tid >= pairs) return;
    const int odd = threadIdx.x & 1;

    // ---- coalesced elev residual (streaming, short-lived regs) ----
    {
        const float2 e2 = __ldcg(((const float2*)elev) + tid);
        const float2 i2 = __ldcg(((const float2*)init_elev) + tid);
        __stcg(((float2*)out_elev) + tid, make_float2(e2.x - i2.x, e2.y - i2.y));
    }

    // ---- per-edge index loads (vectorized across the 2 edges) ----
    const int2 sp = __ldcg(((const int2*)src_idx)   + tid);
    const int2 tp = __ldcg(((const int2*)tgt_idx)   + tid);
    const int2 pp = __ldcg(((const int2*)patch_idx) + tid);

    // ---- patch gathers for BOTH edges up front (long-latency, max MLP) ----
    const float2* patch2  = (const float2*)patch_coords;
    const float2* target2 = (const float2*)target;
    const float2 pc0 = __ldcg(patch2 + pp.x);
    const float2 pc1 = __ldcg(patch2 + pp.y);
    const float  ph0 = __ldcg(elev + pp.x);
    const float  ph1 = __ldcg(elev + pp.y);

    // ---- edge 0: paired pose gathers + math; target loaded at point of use ----
    float2 r0, r1;
    {
        float4 sa, sb, ta, tb;
        gather_pose_paired(sp.x, odd, sa, sb);
        gather_pose_paired(tp.x, odd, ta, tb);
        const float2 tg0 = __ldcg(target2 + 2 * tid);
        r0 = finish_edge(pc0, ph0, sa, sb, ta, tb, tg0);
    }
    // ---- edge 1 ----
    {
        float4 sa, sb, ta, tb;
        gather_pose_paired(sp.y, odd, sa, sb);
        gather_pose_paired(tp.y, odd, ta, tb);
        const float2 tg1 = __ldcg(target2 + 2 * tid + 1);
        r1 = finish_edge(pc1, ph1, sa, sb, ta, tb, tg1);
    }

    __stcg(((float4*)out) + tid, make_float4(r0.x, r0.y, r1.x, r1.y));
}

extern "C" void kernel_launch(void* const* d_in, const int* in_sizes, int n_in,
                              void* d_out, int out_size)
{
    const float* poses        = (const float*)d_in[0];
    const float* init_poses   = (const float*)d_in[1];
    const float* patch_coords = (const float*)d_in[2];
    const float* elev         = (const float*)d_in[3];
    const float* init_elev    = (const float*)d_in[4];
    const float* target       = (const float*)d_in[5];
    const int*   src_idx      = (const int*)d_in[6];
    const int*   tgt_idx      = (const int*)d_in[7];
    const int*   patch_idx    = (const int*)d_in[8];
    float*       out          = (float*)d_out;

    const int E  = in_sizes[8];   // 4194304
    const int P7 = in_sizes[0];   // 57344
    const long long proj_elems = 2LL * E;

    // tiny pose prepass
    {
        const int threads = 256;
        const int work = P7 >> 2;  // 14336 threads (covers P_NUM=8192)
        const int blocks = (work + threads - 1) / threads;
        pose_prepass<<<blocks, threads>>>(poses, init_poses, out + proj_elems, P7);
    }

    // main: 2 edges/thread, paired pose gathers, natural register allocation
    {
        const int threads = 256;
        const int pairs = E >> 1;
        const int blocks = (pairs + threads - 1) / threads;
        ba_main<<<blocks, threads>>>(
            patch_coords, elev, init_elev, target,
            src_idx, tgt_idx, patch_idx,
            out, out + proj_elems + P7, E);
    }
}

// round 17
// speedup vs baseline: 1.5510x; 1.5510x over previous
#include <cuda_runtime.h>
#include <cuda_bf16.h>

// BundleAdjustment, FINAL (= round-12 optimum, byte-identical revert).
//  - paired pose gathers: poses stored as contiguous 32B entries; lane pairs
//    cooperatively load both 16B halves so each LDG.128 touches 16 lines
//    instead of 32; halves exchanged via shfl.xor (bit-exact).
//    -> divergent gather line-units/edge at the exact-arithmetic minimum (~4.4)
//  - 2 edges/thread, batched patch gathers for MLP, __ldcg/__stcg cache split
//  - natural register allocation (34 regs, 67% occ): forced caps spill (R13),
//    restructuring regresses the allocator (R14) -- both proven losers.

#define R_MIN   0.5f
#define R_MAX   30.0f
#define BINS    512.0f
#define BEAMS   512.0f
#define FOV_H   2.0943951f

#define P_NUM   8192

// Scratch: pose table, 32B per pose: [2i]=(tx,ty,tz,qx)  [2i+1]=(qy,qz,qw,0)
__device__ float4 g_pose[2 * P_NUM];   // 256 KB

// ---------------- Tiny pose prepass ----------------
__global__ __launch_bounds__(256) void pose_prepass(
    const float* __restrict__ poses,
    const float* __restrict__ init_poses,
    float*       __restrict__ out_pose,      // out + 2E
    int P7)
{
    const int tid = blockIdx.x * blockDim.x + threadIdx.x;
    const int nv  = P7 >> 2;                 // 14336 float4 residuals
    if (tid < nv) {
        const float4 a = __ldcg(((const float4*)poses) + tid);
        const float4 b = __ldcg(((const float4*)init_poses) + tid);
        float4 r = make_float4(a.x - b.x, a.y - b.y, a.z - b.z, a.w - b.w);
        __stcg(((float4*)out_pose) + tid, r);
    }
    if (tid < P_NUM) {
        const float* p = poses + 7 * tid;
        g_pose[2 * tid]     = make_float4(p[0], p[1], p[2], p[3]);
        g_pose[2 * tid + 1] = make_float4(p[4], p[5], p[6], 0.0f);
    }
}

// ---------------- Main ----------------
__device__ __forceinline__ float4 shfl_xor_f4(float4 v, int m)
{
    float4 r;
    r.x = __shfl_xor_sync(0xFFFFFFFFu, v.x, m);
    r.y = __shfl_xor_sync(0xFFFFFFFFu, v.y, m);
    r.z = __shfl_xor_sync(0xFFFFFFFFu, v.z, m);
    r.w = __shfl_xor_sync(0xFFFFFFFFu, v.w, m);
    return r;
}

// Cooperatively gather pose[idx] (32B) per lane via lane-pairing. Bit-exact.
__device__ __forceinline__ void gather_pose_paired(int idx, int odd,
                                                   float4& lo, float4& hi)
{
    const int idx_part = __shfl_xor_sync(0xFFFFFFFFu, idx, 1);
    const int s_even = odd ? idx_part : idx;
    const int s_odd  = odd ? idx      : idx_part;

    const float4 fa = __ldg(&g_pose[2 * s_even + odd]);  // pair covers both halves of pose[s_even]
    const float4 fb = __ldg(&g_pose[2 * s_odd + odd]);   // pair covers both halves of pose[s_odd]

    const float4 fa_x = shfl_xor_f4(fa, 1);
    const float4 fb_x = shfl_xor_f4(fb, 1);

    lo = odd ? fb_x : fa;
    hi = odd ? fb   : fa_x;
}

__device__ __forceinline__ float2 finish_edge(float2 pc, float ph,
                                              const float4& sa, const float4& sb,
                                              const float4& ta, const float4& tb,
                                              float2 tg)
{
    float st, ct, sph, cph;
    __sincosf(pc.y, &st, &ct);
    __sincosf(ph,   &sph, &cph);
    const float rcp = pc.x * cph;
    float vx = rcp * ct;
    float vy = rcp * st;
    float vz = pc.x * sph;

    {
        const float qx = sa.w, qy = sb.x, qz = sb.y, qw = sb.z;
        const float tx = 2.0f * (qy * vz - qz * vy);
        const float ty = 2.0f * (qz * vx - qx * vz);
        const float tz = 2.0f * (qx * vy - qy * vx);
        const float rx = vx + qw * tx + (qy * tz - qz * ty);
        const float ry = vy + qw * ty + (qz * tx - qx * tz);
        const float rz = vz + qw * tz + (qx * ty - qy * tx);
        vx = rx + sa.x; vy = ry + sa.y; vz = rz + sa.z;
    }

    vx -= ta.x; vy -= ta.y; vz -= ta.z;
    float lx, ly, lz;
    {
        const float qx = -ta.w, qy = -tb.x, qz = -tb.y, qw = tb.z;
        const float tx = 2.0f * (qy * vz - qz * vy);
        const float ty = 2.0f * (qz * vx - qx * vz);
        const float tz = 2.0f * (qx * vy - qy * vx);
        lx = vx + qw * tx + (qy * tz - qz * ty);
        ly = vy + qw * ty + (qz * tx - qx * tz);
        lz = vz + qw * tz + (qx * ty - qy * tx);
    }

    const float r3 = sqrtf(lx * lx + ly * ly + lz * lz);
    const float th = atan2f(ly, lx);

    float2 res;
    res.x = (r3 - tg.x) * (BINS  / (R_MAX - R_MIN));
    res.y = (th - tg.y) * (BEAMS / FOV_H);
    return res;
}

__global__ __launch_bounds__(256) void ba_main(
    const float* __restrict__ patch_coords,  // float2 per patch
    const float* __restrict__ elev,
    const float* __restrict__ init_elev,
    const float* __restrict__ target,        // float2 per edge
    const int*   __restrict__ src_idx,
    const int*   __restrict__ tgt_idx,
    const int*   __restrict__ patch_idx,
    float*       __restrict__ out,           // residual_proj base
    float*       __restrict__ out_elev,      // out + 2E + P7
    int E)
{
    const int tid   = blockIdx.x * blockDim.x + threadIdx.x;
    const int pairs = E >> 1;                // E % 512 == 0: whole warps only
    if (tid >= pairs) return;
    const int odd = threadIdx.x & 1;

    // ---- coalesced elev residual (streaming, 2 elems) ----
    {
        const float2 e2 = __ldcg(((const float2*)elev) + tid);
        const float2 i2 = __ldcg(((const float2*)init_elev) + tid);
        __stcg(((float2*)out_elev) + tid, make_float2(e2.x - i2.x, e2.y - i2.y));
    }

    // ---- sequential per-edge loads (vectorized across the 2 edges) ----
    const int2   sp = __ldcg(((const int2*)src_idx)   + tid);
    const int2   tp = __ldcg(((const int2*)tgt_idx)   + tid);
    const int2   pp = __ldcg(((const int2*)patch_idx) + tid);
    const float4 tg = __ldcg(((const float4*)target)  + tid);

    // ---- patch gathers for BOTH edges up front (long-latency, max MLP) ----
    const float2* patch2 = (const float2*)patch_coords;
    const float2 pc0 = __ldcg(patch2 + pp.x);
    const float2 pc1 = __ldcg(patch2 + pp.y);
    const float  ph0 = __ldcg(elev + pp.x);
    const float  ph1 = __ldcg(elev + pp.y);

    // ---- edge 0: paired pose gathers + math (frees pose regs before edge 1) ----
    float2 r0, r1;
    {
        float4 sa, sb, ta, tb;
        gather_pose_paired(sp.x, odd, sa, sb);
        gather_pose_paired(tp.x, odd, ta, tb);
        r0 = finish_edge(pc0, ph0, sa, sb, ta, tb, make_float2(tg.x, tg.y));
    }
    // ---- edge 1 ----
    {
        float4 sa, sb, ta, tb;
        gather_pose_paired(sp.y, odd, sa, sb);
        gather_pose_paired(tp.y, odd, ta, tb);
        r1 = finish_edge(pc1, ph1, sa, sb, ta, tb, make_float2(tg.z, tg.w));
    }

    __stcg(((float4*)out) + tid, make_float4(r0.x, r0.y, r1.x, r1.y));
}

extern "C" void kernel_launch(void* const* d_in, const int* in_sizes, int n_in,
                              void* d_out, int out_size)
{
    const float* poses        = (const float*)d_in[0];
    const float* init_poses   = (const float*)d_in[1];
    const float* patch_coords = (const float*)d_in[2];
    const float* elev         = (const float*)d_in[3];
    const float* init_elev    = (const float*)d_in[4];
    const float* target       = (const float*)d_in[5];
    const int*   src_idx      = (const int*)d_in[6];
    const int*   tgt_idx      = (const int*)d_in[7];
    const int*   patch_idx    = (const int*)d_in[8];
    float*       out          = (float*)d_out;

    const int E  = in_sizes[8];   // 4194304
    const int P7 = in_sizes[0];   // 57344
    const long long proj_elems = 2LL * E;

    // tiny pose prepass
    {
        const int threads = 256;
        const int work = P7 >> 2;  // 14336 threads (covers P_NUM=8192)
        const int blocks = (work + threads - 1) / threads;
        pose_prepass<<<blocks, threads>>>(poses, init_poses, out + proj_elems, P7);
    }

    // main: 2 edges/thread, paired pose gathers, streaming stores
    {
        const int threads = 256;
        const int pairs = E >> 1;
        const int blocks = (pairs + threads - 1) / threads;
        ba_main<<<blocks, threads>>>(
            patch_coords, elev, init_elev, target,
            src_idx, tgt_idx, patch_idx,
            out, out + proj_elems + P7, E);
    }
}